// round 1
// baseline (speedup 1.0000x reference)
#include <cuda_runtime.h>
#include <math.h>

#define C_DIM   256
#define H_DIM   8
#define B_GRAPHS 2048
#define NPG_    128
#define N_NODES (B_GRAPHS * NPG_)
#define EPS_    1e-5f
#define ATTN_SCALE 0.17677669529663687f   /* 1/sqrt(32) */

// ---------------- scratch (device globals; no allocation allowed) ----------------
__device__ float g_h1[(size_t)N_NODES * C_DIM];   // 256 MB scratch for h1
__device__ float g_sum[C_DIM];
__device__ float g_sumsq[C_DIM];
__device__ float g_na[C_DIM];     // per-channel norm scale  gamma*rsqrt(var+eps)
__device__ float g_nd[C_DIM];     // per-channel norm shift  beta - mu*na
__device__ float g_w16[16 * C_DIM]; // e<8: scale*wk_eff[h][:], e>=8: wv_eff[h][:]
__device__ float g_b16[16];         // e<8: scale*blog[h],      e>=8: bs[h]
__device__ float g_c0;              // Wr.bo + br

// ---------------- f32x2 packed-FMA helpers (sm_103a dual-fp32 path) --------------
__device__ __forceinline__ unsigned long long f2pack(float lo, float hi) {
    unsigned long long r;
    asm("mov.b64 %0, {%1, %2};" : "=l"(r) : "f"(lo), "f"(hi));
    return r;
}
__device__ __forceinline__ void ffma2(unsigned long long& d,
                                      unsigned long long a, unsigned long long b) {
    asm("fma.rn.f32x2 %0, %1, %2, %0;" : "+l"(d) : "l"(a), "l"(b));
}
__device__ __forceinline__ void f2unpack(unsigned long long v, float& lo, float& hi) {
    asm("mov.b64 {%0, %1}, %2;" : "=f"(lo), "=f"(hi) : "l"(v));
}

// ---------------- kernel Z: zero the stats accumulators --------------------------
__global__ void kZero() {
    int t = threadIdx.x;
    if (t < C_DIM) { g_sum[t] = 0.f; g_sumsq[t] = 0.f; }
}

// ---------------- kernel A: h1 = x @ W1^T + b1, + column sum/sumsq ---------------
// grid (2048, 2), block 256.  BM=128, BN=128, BK=16, per-thread 8x8 via f32x2.
__global__ void __launch_bounds__(256, 2)
kA(const float* __restrict__ x, const float* __restrict__ W1, const float* __restrict__ b1)
{
    __shared__ __align__(16) float xs[2][128][16];   // [m][k]
    __shared__ __align__(16) float ws[2][16][128];   // [k][n]  (n-pairs contiguous)
    __shared__ float csum[128];
    __shared__ float csq[128];

    const int t = threadIdx.x;
    const int rowbase = blockIdx.x * 128;
    const int colbase = blockIdx.y * 128;
    const int tn = t & 15, tm = t >> 4;
    const int j0 = tn * 8, m0 = tm * 8;

    unsigned long long acc[8][4];
#pragma unroll
    for (int mm = 0; mm < 8; ++mm)
#pragma unroll
        for (int p = 0; p < 4; ++p) acc[mm][p] = 0ULL;

    // prologue: chunk 0 into buffer 0
#pragma unroll
    for (int i = 0; i < 2; ++i) {
        int f = t + 256 * i;
        int r = f >> 2;
        int c4 = (f & 3) * 4;
        float4 vx = *(const float4*)&x[(size_t)(rowbase + r) * 256 + c4];
        *(float4*)&xs[0][r][c4] = vx;
        float4 vw = *(const float4*)&W1[(size_t)(colbase + r) * 256 + c4];
        ws[0][c4 + 0][r] = vw.x; ws[0][c4 + 1][r] = vw.y;
        ws[0][c4 + 2][r] = vw.z; ws[0][c4 + 3][r] = vw.w;
    }
    __syncthreads();

    float4 pfx[2], pfw[2];
    for (int ch = 0; ch < 16; ++ch) {
        const int cur = ch & 1;
        if (ch < 15) {
            const int kc = (ch + 1) * 16;
#pragma unroll
            for (int i = 0; i < 2; ++i) {
                int f = t + 256 * i;
                int r = f >> 2;
                int c4 = (f & 3) * 4;
                pfx[i] = *(const float4*)&x[(size_t)(rowbase + r) * 256 + kc + c4];
                pfw[i] = *(const float4*)&W1[(size_t)(colbase + r) * 256 + kc + c4];
            }
        }
#pragma unroll
        for (int kk = 0; kk < 16; ++kk) {
            unsigned long long av[8];
#pragma unroll
            for (int mm = 0; mm < 8; ++mm) {
                float a = xs[cur][m0 + mm][kk];
                av[mm] = f2pack(a, a);
            }
            unsigned long long bv[4];
            const unsigned long long* wrow = (const unsigned long long*)&ws[cur][kk][j0];
#pragma unroll
            for (int p = 0; p < 4; ++p) bv[p] = wrow[p];
#pragma unroll
            for (int mm = 0; mm < 8; ++mm)
#pragma unroll
                for (int p = 0; p < 4; ++p) ffma2(acc[mm][p], av[mm], bv[p]);
        }
        __syncthreads();
        if (ch < 15) {
            const int nxt = cur ^ 1;
#pragma unroll
            for (int i = 0; i < 2; ++i) {
                int f = t + 256 * i;
                int r = f >> 2;
                int c4 = (f & 3) * 4;
                *(float4*)&xs[nxt][r][c4] = pfx[i];
                ws[nxt][c4 + 0][r] = pfw[i].x; ws[nxt][c4 + 1][r] = pfw[i].y;
                ws[nxt][c4 + 2][r] = pfw[i].z; ws[nxt][c4 + 3][r] = pfw[i].w;
            }
            __syncthreads();
        }
    }

    // epilogue: +b1, store h1, accumulate per-column sum / sumsq
    float b1v[8];
#pragma unroll
    for (int jj = 0; jj < 8; ++jj) b1v[jj] = b1[colbase + j0 + jj];

    float cs[8], cq[8];
#pragma unroll
    for (int jj = 0; jj < 8; ++jj) { cs[jj] = 0.f; cq[jj] = 0.f; }

#pragma unroll
    for (int mm = 0; mm < 8; ++mm) {
        float v[8];
#pragma unroll
        for (int p = 0; p < 4; ++p) {
            float lo, hi;
            f2unpack(acc[mm][p], lo, hi);
            v[2 * p]     = lo + b1v[2 * p];
            v[2 * p + 1] = hi + b1v[2 * p + 1];
        }
        size_t base = (size_t)(rowbase + m0 + mm) * 256 + colbase + j0;
        *(float4*)&g_h1[base]     = make_float4(v[0], v[1], v[2], v[3]);
        *(float4*)&g_h1[base + 4] = make_float4(v[4], v[5], v[6], v[7]);
#pragma unroll
        for (int jj = 0; jj < 8; ++jj) { cs[jj] += v[jj]; cq[jj] += v[jj] * v[jj]; }
    }

    if (t < 128) { csum[t] = 0.f; csq[t] = 0.f; }
    __syncthreads();
#pragma unroll
    for (int jj = 0; jj < 8; ++jj) {
        atomicAdd(&csum[j0 + jj], cs[jj]);
        atomicAdd(&csq[j0 + jj],  cq[jj]);
    }
    __syncthreads();
    if (t < 128) {
        atomicAdd(&g_sum[colbase + t],   csum[t]);
        atomicAdd(&g_sumsq[colbase + t], csq[t]);
    }
}

// ---------------- kernel B: finalize stats + fold all small weights --------------
// 1 block, 256 threads.
__global__ void kB(const float* __restrict__ gamma, const float* __restrict__ beta,
                   const float* __restrict__ Wq, const float* __restrict__ bq,
                   const float* __restrict__ Wk, const float* __restrict__ bk,
                   const float* __restrict__ Wv, const float* __restrict__ bv,
                   const float* __restrict__ Wo, const float* __restrict__ bo,
                   const float* __restrict__ Wr, const float* __restrict__ br)
{
    __shared__ float qv[256], we[256], wrs[256];
    const int t = threadIdx.x;
    const float invN = 1.0f / (float)N_NODES;

    float mean = g_sum[t] * invN;
    float var  = g_sumsq[t] * invN - mean * mean;
    float rs   = rsqrtf(var + EPS_);
    float na   = gamma[t] * rs;
    g_na[t] = na;
    g_nd[t] = beta[t] - mean * na;

    // qh = rowsum(Wq) + bq   (q == ones)
    float s = bq[t];
    for (int j = 0; j < 256; ++j) s += Wq[(size_t)t * 256 + j];
    qv[t]  = s;
    wrs[t] = Wr[t];
    __syncthreads();

    // weff = Wr @ Wo   (1 x C)
    float e = 0.f;
    for (int j = 0; j < 256; ++j) e += wrs[j] * Wo[(size_t)j * 256 + t];
    we[t] = e;
    __syncthreads();

    // wk_eff / wv_eff, prescaled
    for (int h = 0; h < 8; ++h) {
        float wk = 0.f, wv_ = 0.f;
        for (int d = 0; d < 32; ++d) {
            int c = h * 32 + d;
            wk  += qv[c] * Wk[(size_t)c * 256 + t];
            wv_ += we[c] * Wv[(size_t)c * 256 + t];
        }
        g_w16[h * 256 + t]       = wk * ATTN_SCALE;
        g_w16[(8 + h) * 256 + t] = wv_;
    }
    if (t < 8) {
        float bl = 0.f, bs = 0.f;
        for (int d = 0; d < 32; ++d) {
            int c = t * 32 + d;
            bl += qv[c] * bk[c];
            bs += we[c] * bv[c];
        }
        g_b16[t]     = bl * ATTN_SCALE;
        g_b16[8 + t] = bs;
    }
    if (t == 0) {
        float c0 = br[0];
        for (int j = 0; j < 256; ++j) c0 += wrs[j] * bo[j];
        g_c0 = c0;
    }
}

// ---------------- kernel C: per-group fused norm/relu/GEMM2/attn/out -------------
// smem layout (floats):
#define YSTRIDE 260
#define YS_OFF   0
#define W2_OFF   (128 * YSTRIDE)                 // 33280
#define W16_OFF  (W2_OFF + 2 * 16 * 256)         // 41472
#define W16STR   260
#define LG_OFF   (W16_OFF + 16 * W16STR)         // 45632
#define LGSTR    17
#define HR_OFF   (LG_OFF + 128 * LGSTR)          // 47808
#define AS_OFF   (HR_OFF + 8)                    // 47816
#define DS_OFF   (AS_OFF + 256)                  // 48072
#define SMC_FLOATS (DS_OFF + 256)                // 48328 floats = 193312 B

__global__ void __launch_bounds__(512, 1)
kC(const float* __restrict__ W2, const float* __restrict__ b2, float* __restrict__ out)
{
    extern __shared__ float sm[];
    const int t = threadIdx.x;
    const int g = blockIdx.x;
    const float* h1 = g_h1 + (size_t)g * (128 * 256);

    if (t < 256) { sm[AS_OFF + t] = g_na[t]; sm[DS_OFF + t] = g_nd[t]; }
    __syncthreads();

    // phase 1: y = relu(na*h1 + nd) -> ys ; also stage w16 into smem
#pragma unroll
    for (int i = 0; i < 16; ++i) {
        int f  = t + 512 * i;
        int r  = f >> 6;
        int c4 = (f & 63) * 4;
        float4 v = *(const float4*)&h1[(size_t)r * 256 + c4];
        v.x = fmaxf(fmaf(v.x, sm[AS_OFF + c4 + 0], sm[DS_OFF + c4 + 0]), 0.f);
        v.y = fmaxf(fmaf(v.y, sm[AS_OFF + c4 + 1], sm[DS_OFF + c4 + 1]), 0.f);
        v.z = fmaxf(fmaf(v.z, sm[AS_OFF + c4 + 2], sm[DS_OFF + c4 + 2]), 0.f);
        v.w = fmaxf(fmaf(v.w, sm[AS_OFF + c4 + 3], sm[DS_OFF + c4 + 3]), 0.f);
        *(float4*)&sm[YS_OFF + r * YSTRIDE + c4] = v;
    }
#pragma unroll
    for (int i = 0; i < 2; ++i) {
        int f  = t + 512 * i;
        int e  = f >> 6;
        int c4 = (f & 63) * 4;
        float4 v = *(const float4*)&g_w16[e * 256 + c4];
        *(float4*)&sm[W16_OFF + e * W16STR + c4] = v;
    }

    // GEMM2 prologue: W2 chunk 0 (transposed store -> [k][j])
#pragma unroll
    for (int i = 0; i < 2; ++i) {
        int f  = t + 512 * i;
        int j  = f >> 2;
        int c4 = (f & 3) * 4;
        float4 v = *(const float4*)&W2[(size_t)j * 256 + c4];
        sm[W2_OFF + (c4 + 0) * 256 + j] = v.x;
        sm[W2_OFF + (c4 + 1) * 256 + j] = v.y;
        sm[W2_OFF + (c4 + 2) * 256 + j] = v.z;
        sm[W2_OFF + (c4 + 3) * 256 + j] = v.w;
    }
    __syncthreads();

    const int tn = t & 31, tm = t >> 5;
    const int j0 = tn * 8, m0 = tm * 8;

    unsigned long long acc[8][4];
#pragma unroll
    for (int mm = 0; mm < 8; ++mm)
#pragma unroll
        for (int p = 0; p < 4; ++p) acc[mm][p] = 0ULL;

    float4 pf[2];
    for (int ch = 0; ch < 16; ++ch) {
        const int cur = ch & 1;
        if (ch < 15) {
            const int kc = (ch + 1) * 16;
#pragma unroll
            for (int i = 0; i < 2; ++i) {
                int f  = t + 512 * i;
                int j  = f >> 2;
                int c4 = (f & 3) * 4;
                pf[i] = *(const float4*)&W2[(size_t)j * 256 + kc + c4];
            }
        }
#pragma unroll
        for (int kk = 0; kk < 16; ++kk) {
            const int k = ch * 16 + kk;
            unsigned long long av[8];
#pragma unroll
            for (int mm = 0; mm < 8; ++mm) {
                float a = sm[YS_OFF + (m0 + mm) * YSTRIDE + k];
                av[mm] = f2pack(a, a);
            }
            unsigned long long bv[4];
            const unsigned long long* wrow =
                (const unsigned long long*)&sm[W2_OFF + cur * 4096 + kk * 256 + j0];
#pragma unroll
            for (int p = 0; p < 4; ++p) bv[p] = wrow[p];
#pragma unroll
            for (int mm = 0; mm < 8; ++mm)
#pragma unroll
                for (int p = 0; p < 4; ++p) ffma2(acc[mm][p], av[mm], bv[p]);
        }
        __syncthreads();
        if (ch < 15) {
            const int nxt = cur ^ 1;
#pragma unroll
            for (int i = 0; i < 2; ++i) {
                int f  = t + 512 * i;
                int j  = f >> 2;
                int c4 = (f & 3) * 4;
                sm[W2_OFF + nxt * 4096 + (c4 + 0) * 256 + j] = pf[i].x;
                sm[W2_OFF + nxt * 4096 + (c4 + 1) * 256 + j] = pf[i].y;
                sm[W2_OFF + nxt * 4096 + (c4 + 2) * 256 + j] = pf[i].z;
                sm[W2_OFF + nxt * 4096 + (c4 + 3) * 256 + j] = pf[i].w;
            }
            __syncthreads();
        }
    }

    // write h2 = acc + b2 into ys (all reads of y are done; synced above)
    {
        float b2v[8];
#pragma unroll
        for (int jj = 0; jj < 8; ++jj) b2v[jj] = b2[j0 + jj];
#pragma unroll
        for (int mm = 0; mm < 8; ++mm) {
            float v[8];
#pragma unroll
            for (int p = 0; p < 4; ++p) {
                float lo, hi;
                f2unpack(acc[mm][p], lo, hi);
                v[2 * p]     = lo + b2v[2 * p];
                v[2 * p + 1] = hi + b2v[2 * p + 1];
            }
            int base = YS_OFF + (m0 + mm) * YSTRIDE + j0;
            *(float4*)&sm[base]     = make_float4(v[0], v[1], v[2], v[3]);
            *(float4*)&sm[base + 4] = make_float4(v[4], v[5], v[6], v[7]);
        }
    }
    __syncthreads();

    // phase 4: skinny GEMM  out16[n][e] = h2[n,:] . w16[e,:] + b16[e]
    {
        const int e  = t & 15;
        const int nb = t >> 4;            // 0..31
        float a4[4] = {0.f, 0.f, 0.f, 0.f};
        const float* wrow = &sm[W16_OFF + e * W16STR];
#pragma unroll 8
        for (int k4 = 0; k4 < 64; ++k4) {
            float4 w = *(const float4*)&wrow[k4 * 4];
#pragma unroll
            for (int i = 0; i < 4; ++i) {
                float4 h = *(const float4*)&sm[YS_OFF + (nb + 32 * i) * YSTRIDE + k4 * 4];
                a4[i] = fmaf(h.x, w.x, a4[i]);
                a4[i] = fmaf(h.y, w.y, a4[i]);
                a4[i] = fmaf(h.z, w.z, a4[i]);
                a4[i] = fmaf(h.w, w.w, a4[i]);
            }
        }
        float bb = g_b16[e];
#pragma unroll
        for (int i = 0; i < 4; ++i)
            sm[LG_OFF + (nb + 32 * i) * LGSTR + e] = a4[i] + bb;
    }
    __syncthreads();

    // phase 5: per-head softmax over the 128-node group + weighted sum of s
    {
        const int w    = t >> 5;
        const int lane = t & 31;
        if (w < 8) {
            float l[4];
#pragma unroll
            for (int i = 0; i < 4; ++i)
                l[i] = sm[LG_OFF + (lane + 32 * i) * LGSTR + w];
            float m = fmaxf(fmaxf(l[0], l[1]), fmaxf(l[2], l[3]));
#pragma unroll
            for (int o = 16; o > 0; o >>= 1)
                m = fmaxf(m, __shfl_xor_sync(0xffffffffu, m, o));
            float ps = 0.f, pv = 0.f;
#pragma unroll
            for (int i = 0; i < 4; ++i) {
                float p = __expf(l[i] - m);
                ps += p;
                pv += p * sm[LG_OFF + (lane + 32 * i) * LGSTR + 8 + w];
            }
#pragma unroll
            for (int o = 16; o > 0; o >>= 1) {
                ps += __shfl_xor_sync(0xffffffffu, ps, o);
                pv += __shfl_xor_sync(0xffffffffu, pv, o);
            }
            if (lane == 0) sm[HR_OFF + w] = pv / ps;
        }
    }
    __syncthreads();
    if (t == 0) {
        float r = g_c0;
#pragma unroll
        for (int h = 0; h < 8; ++h) r += sm[HR_OFF + h];
        out[g] = tanhf(r);
    }
}

// ---------------- launch -----------------------------------------------------------
extern "C" void kernel_launch(void* const* d_in, const int* in_sizes, int n_in,
                              void* d_out, int out_size)
{
    // x, batch, [num_graphs], then 16 weight/bias tensors (W1..br).
    const int base = n_in - 16;
    const float* x     = (const float*)d_in[0];
    const float* W1    = (const float*)d_in[base + 0];
    const float* b1    = (const float*)d_in[base + 1];
    const float* gamma = (const float*)d_in[base + 2];
    const float* beta  = (const float*)d_in[base + 3];
    const float* W2    = (const float*)d_in[base + 4];
    const float* b2    = (const float*)d_in[base + 5];
    const float* Wq    = (const float*)d_in[base + 6];
    const float* bq    = (const float*)d_in[base + 7];
    const float* Wk    = (const float*)d_in[base + 8];
    const float* bk    = (const float*)d_in[base + 9];
    const float* Wv    = (const float*)d_in[base + 10];
    const float* bv    = (const float*)d_in[base + 11];
    const float* Wo    = (const float*)d_in[base + 12];
    const float* bo    = (const float*)d_in[base + 13];
    const float* Wr    = (const float*)d_in[base + 14];
    const float* br    = (const float*)d_in[base + 15];

    kZero<<<1, 256>>>();
    dim3 gA(B_GRAPHS, 2);
    kA<<<gA, 256>>>(x, W1, b1);
    kB<<<1, 256>>>(gamma, beta, Wq, bq, Wk, bk, Wv, bv, Wo, bo, Wr, br);

    const size_t shc = (size_t)SMC_FLOATS * sizeof(float);
    cudaFuncSetAttribute((const void*)kC,
                         cudaFuncAttributeMaxDynamicSharedMemorySize, (int)shc);
    kC<<<B_GRAPHS, 512, shc>>>(W2, b2, (float*)d_out);
}